// round 1
// baseline (speedup 1.0000x reference)
#include <cuda_runtime.h>

#define T_  256
#define NN  4000
#define DM  178
#define DI  46
#define H_  64
#define DH  64
#define FF  110   // DI + H
#define G4  256   // 4*H
#define TILE 128
#define NTILES 32 // ceil(4000/128)

typedef unsigned long long u64;

// ---------- device scratch (no allocations allowed) ----------
__device__ float g_XZ[T_ * G4];      // precomputed input projection of LSTM
__device__ float g_WT[DM * G4];      // W_ih transposed [j][g]
__device__ float g_hseq[T_ * H_];    // LSTM hidden states
__device__ float g_macro1[T_ * DH];  // b1 + W1[:,DI:]@h_t  per t
__device__ float g_sum[T_];
__device__ float g_cnt[T_];
__device__ int   g_mask_kind;        // 0=uint8/bool, 1=int32, 2=float32

// ---------- packed f32x2 helpers ----------
__device__ __forceinline__ u64 pk2(float lo, float hi) {
    u64 r; asm("mov.b64 %0, {%1, %2};" : "=l"(r) : "f"(lo), "f"(hi)); return r;
}
__device__ __forceinline__ u64 ffma2(u64 a, u64 b, u64 c) {
    u64 d; asm("fma.rn.f32x2 %0, %1, %2, %3;" : "=l"(d) : "l"(a), "l"(b), "l"(c)); return d;
}
__device__ __forceinline__ float2 up2(u64 a) {
    float2 f; asm("mov.b64 {%0, %1}, %2;" : "=f"(f.x), "=f"(f.y) : "l"(a)); return f;
}

// ---------- fast-but-accurate activations (ex2.approx + rcp: ~1e-6 rel err) ----------
__device__ __forceinline__ float sigm(float x) {
    float e = exp2f(-1.44269504088896340736f * x);
    return __fdividef(1.0f, 1.0f + e);
}
__device__ __forceinline__ float tanh_(float x) {
    float a = fabsf(x);
    float e = exp2f(-2.88539008177792681472f * a);   // exp(-2a)
    float r = __fdividef(1.0f - e, 1.0f + e);
    return copysignf(r, x);
}

// ---------- K0: transpose W_ih + mask dtype detection ----------
__global__ void k_trans(const float* __restrict__ W_ih,
                        const unsigned char* __restrict__ masks) {
    int idx = blockIdx.x * 256 + threadIdx.x;
    if (idx < DM * G4) {
        int g = idx / DM, j = idx % DM;
        g_WT[j * G4 + g] = W_ih[idx];
    }
    if (blockIdx.x == 0) {
        __shared__ int s_any, s_flt;
        if (threadIdx.x == 0) { s_any = 0; s_flt = 0; }
        __syncthreads();
        int ta = 0, tf = 0;
        for (int j = threadIdx.x; j < 1024; j += 256) {
            unsigned char c1 = masks[4*j+1], c2 = masks[4*j+2], c3 = masks[4*j+3];
            if (c1 | c2 | c3) ta = 1;
            if (c3 == 0x3F) tf = 1;   // bytes of 1.0f = 00 00 80 3F
        }
        if (ta) atomicOr(&s_any, 1);
        if (tf) atomicOr(&s_flt, 1);
        __syncthreads();
        if (threadIdx.x == 0)
            g_mask_kind = s_flt ? 2 : (s_any ? 0 : 1);
    }
}

// ---------- K1: XZ = macro @ W_ih^T + (b_ih+b_hh); also zero accumulators ----------
__global__ void __launch_bounds__(256) k_prep(const float* __restrict__ macro,
                                              const float* __restrict__ b_ih,
                                              const float* __restrict__ b_hh) {
    __shared__ float xs[DM];
    int t = blockIdx.x, g = threadIdx.x;
    if (g < DM) xs[g] = macro[t * DM + g];
    if (g == 0) { g_sum[t] = 0.f; g_cnt[t] = 0.f; }
    __syncthreads();
    float acc = b_ih[g] + b_hh[g];
#pragma unroll 2
    for (int j = 0; j < DM; j++)
        acc = fmaf(xs[j], g_WT[j * G4 + g], acc);
    g_XZ[t * G4 + g] = acc;
}

// ---------- K2: sequential LSTM scan (single block) ----------
__global__ void __launch_bounds__(256) k_lstm(const float* __restrict__ W_hh) {
    __shared__ float h_s[H_];
    __shared__ float gact[G4];
    const int g = threadIdx.x;

    u64 w[32];  // thread's W_hh row, packed pairs
    {
        const float2* wr = (const float2*)(W_hh + g * H_);
#pragma unroll
        for (int j = 0; j < 32; j++) { float2 v = wr[j]; w[j] = pk2(v.x, v.y); }
    }
    float c = 0.f;
    if (g < H_) h_s[g] = 0.f;
    float zA = g_XZ[g];
    float zB = g_XZ[G4 + g];
    __syncthreads();

    auto do_step = [&](float zc, int t) {
        u64 a2 = pk2(0.f, 0.f);
#pragma unroll
        for (int j = 0; j < 32; j++) {
            float2 hv = ((const float2*)h_s)[j];
            a2 = ffma2(w[j], pk2(hv.x, hv.y), a2);
        }
        float2 s = up2(a2);
        float z = zc + s.x + s.y;
        float a = (g < 2 * H_ || g >= 3 * H_) ? sigm(z) : tanh_(z);
        gact[g] = a;
        __syncthreads();
        if (g < H_) {
            float iv = gact[g], fv = gact[H_ + g], gv = gact[2*H_ + g], ov = gact[3*H_ + g];
            c = fmaf(fv, c, iv * gv);
            float h = ov * tanh_(c);
            h_s[g] = h;
            g_hseq[t * H_ + g] = h;
        }
        __syncthreads();
    };

    for (int t = 0; t < T_; t += 2) {
        {   // even step, prefetch t+2
            float zc = zA;
            if (t + 2 < T_) zA = g_XZ[(t + 2) * G4 + g];
            do_step(zc, t);
        }
        {   // odd step, prefetch t+3
            float zc = zB;
            if (t + 3 < T_) zB = g_XZ[(t + 3) * G4 + g];
            do_step(zc, t + 1);
        }
    }
}

// ---------- K3: macro1[t][o] = b1[o] + W1[o][DI:] @ h_t ----------
__global__ void __launch_bounds__(64) k_macro1(const float* __restrict__ W1,
                                               const float* __restrict__ b1) {
    __shared__ float hs[H_];
    int t = blockIdx.x, o = threadIdx.x;
    hs[o] = g_hseq[t * H_ + o];
    __syncthreads();
    float acc = b1[o];
    const float* wr = W1 + o * FF + DI;
#pragma unroll 4
    for (int j = 0; j < H_; j++)
        acc = fmaf(hs[j], wr[j], acc);
    g_macro1[t * DH + o] = acc;
}

// ---------- K4: the big pointwise MLP (two smem GEMMs, FFMA2) ----------
// smem floats: XA 64*128 (Xs/A1s union) | W1T 46*64 | W2T 64*64 | W3s 64 | m1s 64 | b2s 64 | red 8*132
#define SMEM_FLOATS (64*128 + 46*64 + 64*64 + 64 + 64 + 64 + 8*132)
#define SMEM_BYTES  (SMEM_FLOATS * 4)

__global__ void __launch_bounds__(128, 3) k_mlp(
    const float* __restrict__ indiv, const unsigned char* __restrict__ mask_raw,
    const float* __restrict__ rets,
    const float* __restrict__ W1, const float* __restrict__ W2,
    const float* __restrict__ b2, const float* __restrict__ W3,
    const float* __restrict__ b3, float* __restrict__ out_w)
{
    extern __shared__ float sm[];
    float* XA  = sm;                  // [64][128]  (Xs rows 0..45, then A1s rows 0..63)
    float* W1T = XA  + DH * TILE;     // [46][64]   W1T[k][o] = W1[o][k]
    float* W2T = W1T + DI * DH;       // [64][64]   W2T[k][o] = W2[o][k]
    float* W3s = W2T + DH * DH;       // [64]
    float* m1s = W3s + DH;            // [64]
    float* b2s = m1s + DH;            // [64]
    float* red = b2s + DH;            // [8][132]

    const int tid = threadIdx.x;
    const int t   = blockIdx.y;
    const int p0  = blockIdx.x * TILE;
    const int px  = tid & 15, oy = tid >> 4;
    const int P0  = px * 8,   O0 = oy * 8;

    // --- stage X tile transposed: Xs[k][p] (zero-pad out-of-range points) ---
    {
        const float2* src = (const float2*)(indiv + (size_t)t * NN * DI);
        for (int idx = tid; idx < TILE * (DI / 2); idx += 128) {
            int p = idx / (DI / 2), kp = idx % (DI / 2);
            float2 v = make_float2(0.f, 0.f);
            if (p0 + p < NN) v = src[(size_t)(p0 + p) * (DI / 2) + kp];
            XA[(2 * kp)     * TILE + p] = v.x;
            XA[(2 * kp + 1) * TILE + p] = v.y;
        }
    }
    // --- stage weights (reads coalesced; smem scatter is cheap, once per tile) ---
    for (int idx = tid; idx < DI * DH; idx += 128) {
        int o = idx / DI, k = idx % DI;
        W1T[k * DH + o] = W1[o * FF + k];
    }
    for (int idx = tid; idx < DH * DH; idx += 128) {
        int o = idx >> 6, k = idx & 63;
        W2T[k * DH + o] = W2[idx];
    }
    if (tid < DH) { W3s[tid] = W3[tid]; m1s[tid] = g_macro1[t * DH + tid]; b2s[tid] = b2[tid]; }
    __syncthreads();

    // --- GEMM1: a1[p][o] = relu( macro1[o] + sum_k Xs[k][p] * W1T[k][o] ) ---
    u64 acc[8][4];
#pragma unroll
    for (int j = 0; j < 8; j++) {
        float m1 = m1s[O0 + j]; u64 m2 = pk2(m1, m1);
#pragma unroll
        for (int i = 0; i < 4; i++) acc[j][i] = m2;
    }
#pragma unroll 2
    for (int k = 0; k < DI; k++) {
        float4 xa = *(const float4*)&XA[k * TILE + P0];
        float4 xb = *(const float4*)&XA[k * TILE + P0 + 4];
        float4 w0 = *(const float4*)&W1T[k * DH + O0];
        float4 w1 = *(const float4*)&W1T[k * DH + O0 + 4];
        u64 xp[4] = { pk2(xa.x, xa.y), pk2(xa.z, xa.w), pk2(xb.x, xb.y), pk2(xb.z, xb.w) };
        float wv[8] = { w0.x, w0.y, w0.z, w0.w, w1.x, w1.y, w1.z, w1.w };
#pragma unroll
        for (int j = 0; j < 8; j++) {
            u64 wd = pk2(wv[j], wv[j]);
#pragma unroll
            for (int i = 0; i < 4; i++) acc[j][i] = ffma2(xp[i], wd, acc[j][i]);
        }
    }
    __syncthreads();   // all Xs reads complete before overwriting with A1s

    // --- relu + store A1s[o][p] (overwrites Xs region) ---
#pragma unroll
    for (int j = 0; j < 8; j++) {
        float2 a0 = up2(acc[j][0]), a1 = up2(acc[j][1]);
        float2 a2 = up2(acc[j][2]), a3 = up2(acc[j][3]);
        float4 v0 = make_float4(fmaxf(a0.x, 0.f), fmaxf(a0.y, 0.f), fmaxf(a1.x, 0.f), fmaxf(a1.y, 0.f));
        float4 v1 = make_float4(fmaxf(a2.x, 0.f), fmaxf(a2.y, 0.f), fmaxf(a3.x, 0.f), fmaxf(a3.y, 0.f));
        *(float4*)&XA[(O0 + j) * TILE + P0]     = v0;
        *(float4*)&XA[(O0 + j) * TILE + P0 + 4] = v1;
    }
    __syncthreads();

    // --- GEMM2: a2[p][o] = b2[o] + sum_k A1s[k][p] * W2T[k][o] ---
#pragma unroll
    for (int j = 0; j < 8; j++) {
        float bb = b2s[O0 + j]; u64 bp = pk2(bb, bb);
#pragma unroll
        for (int i = 0; i < 4; i++) acc[j][i] = bp;
    }
#pragma unroll 2
    for (int k = 0; k < DH; k++) {
        float4 xa = *(const float4*)&XA[k * TILE + P0];
        float4 xb = *(const float4*)&XA[k * TILE + P0 + 4];
        float4 w0 = *(const float4*)&W2T[k * DH + O0];
        float4 w1 = *(const float4*)&W2T[k * DH + O0 + 4];
        u64 xp[4] = { pk2(xa.x, xa.y), pk2(xa.z, xa.w), pk2(xb.x, xb.y), pk2(xb.z, xb.w) };
        float wv[8] = { w0.x, w0.y, w0.z, w0.w, w1.x, w1.y, w1.z, w1.w };
#pragma unroll
        for (int j = 0; j < 8; j++) {
            u64 wd = pk2(wv[j], wv[j]);
#pragma unroll
            for (int i = 0; i < 4; i++) acc[j][i] = ffma2(xp[i], wd, acc[j][i]);
        }
    }

    // --- layer3 partials: sum_j W3[o] * relu(a2) ---
    float wp[8];
#pragma unroll
    for (int i = 0; i < 8; i++) wp[i] = 0.f;
#pragma unroll
    for (int j = 0; j < 8; j++) {
        float w3v = W3s[O0 + j];
#pragma unroll
        for (int i = 0; i < 4; i++) {
            float2 a = up2(acc[j][i]);
            wp[2*i]   = fmaf(w3v, fmaxf(a.x, 0.f), wp[2*i]);
            wp[2*i+1] = fmaf(w3v, fmaxf(a.y, 0.f), wp[2*i+1]);
        }
    }
#pragma unroll
    for (int i = 0; i < 8; i++) red[oy * 132 + P0 + i] = wp[i];
    __syncthreads();

    // --- per-point finish: reduce over oy groups, mask, write, accumulate ---
    float contrib = 0.f, mval = 0.f;
    {
        const int p  = tid;
        const int pg = p0 + p;
        float w = b3[0];
#pragma unroll
        for (int r = 0; r < 8; r++) w += red[r * 132 + p];
        if (pg < NN) {
            int gi = t * NN + pg;
            int kind = g_mask_kind;
            float mf;
            if (kind == 0)      mf = (float)mask_raw[gi];
            else if (kind == 1) mf = (float)((const int*)mask_raw)[gi];
            else                mf = ((const float*)mask_raw)[gi];
            float wm = w * mf;
            out_w[gi] = wm;
            contrib = wm * rets[gi];
            mval = mf;
        }
    }
#pragma unroll
    for (int off = 16; off > 0; off >>= 1) {
        contrib += __shfl_down_sync(0xffffffffu, contrib, off);
        mval    += __shfl_down_sync(0xffffffffu, mval, off);
    }
    __syncthreads();   // done with red before reuse
    int lane = tid & 31, wrp = tid >> 5;
    if (lane == 0) { red[wrp] = contrib; red[8 + wrp] = mval; }
    __syncthreads();
    if (tid == 0) {
        float s = red[0] + red[1] + red[2] + red[3];
        float m = red[8] + red[9] + red[10] + red[11];
        atomicAdd(&g_sum[t], s);
        atomicAdd(&g_cnt[t], m);
    }
}

// ---------- K5: sdf finalize ----------
__global__ void __launch_bounds__(256) k_final(float* __restrict__ out_sdf) {
    __shared__ float smr[256];
    int t = threadIdx.x;
    float cnt = g_cnt[t];
    smr[t] = cnt;
    __syncthreads();
    for (int s = 128; s > 0; s >>= 1) {
        if (t < s) smr[t] += smr[t + s];
        __syncthreads();
    }
    float mean = smr[0] * (1.0f / 256.0f);
    out_sdf[t] = g_sum[t] / cnt * mean + 1.0f;
}

// ---------- launch ----------
extern "C" void kernel_launch(void* const* d_in, const int* in_sizes, int n_in,
                              void* d_out, int out_size) {
    (void)in_sizes; (void)n_in; (void)out_size;
    const float* macro = (const float*)d_in[0];
    const float* indiv = (const float*)d_in[1];
    const unsigned char* masks = (const unsigned char*)d_in[2];
    const float* rets  = (const float*)d_in[3];
    const float* W_ih  = (const float*)d_in[4];
    const float* W_hh  = (const float*)d_in[5];
    const float* b_ih  = (const float*)d_in[6];
    const float* b_hh  = (const float*)d_in[7];
    const float* W1    = (const float*)d_in[8];
    const float* b1    = (const float*)d_in[9];
    const float* W2    = (const float*)d_in[10];
    const float* b2    = (const float*)d_in[11];
    const float* W3    = (const float*)d_in[12];
    const float* b3    = (const float*)d_in[13];

    float* out   = (float*)d_out;
    float* out_sdf = out;          // sdf: [T,1] first (reference return order)
    float* out_w   = out + T_;     // weights: [1,T,N,1]

    cudaFuncSetAttribute(k_mlp, cudaFuncAttributeMaxDynamicSharedMemorySize, SMEM_BYTES);

    k_trans<<<(DM * G4 + 255) / 256, 256>>>(W_ih, masks);
    k_prep<<<T_, G4>>>(macro, b_ih, b_hh);
    k_lstm<<<1, G4>>>(W_hh);
    k_macro1<<<T_, H_>>>(W1, b1);
    dim3 grid(NTILES, T_);
    k_mlp<<<grid, 128, SMEM_BYTES>>>(indiv, masks, rets, W1, W2, b2, W3, b3, out_w);
    k_final<<<1, T_>>>(out_sdf);
}

// round 3
// speedup vs baseline: 2.3532x; 2.3532x over previous
#include <cuda_runtime.h>
#include <cuda_bf16.h>
#include <cstdint>

#define T_  256
#define NN  4000
#define DM  178
#define DI  46
#define H_  64
#define DH  64
#define FF  110   // DI + H
#define G4  256   // 4*H
#define TILE 128
#define NTILES (T_ * 32)   // 8192
#define GRID_MLP 296

typedef unsigned long long u64;

// ---------- device scratch ----------
__device__ float g_XZ[T_ * G4];
__device__ float g_hseq[T_ * H_];
__device__ float g_macro1[T_ * DH];
__device__ float g_sum[T_];
__device__ float g_cnt[T_];
__device__ int   g_mask_kind;   // 0=uint8/bool, 1=int32, 2=float32

// ---------- packed f32x2 helpers (LSTM) ----------
__device__ __forceinline__ u64 pk2(float lo, float hi) {
    u64 r; asm("mov.b64 %0, {%1, %2};" : "=l"(r) : "f"(lo), "f"(hi)); return r;
}
__device__ __forceinline__ u64 ffma2(u64 a, u64 b, u64 c) {
    u64 d; asm("fma.rn.f32x2 %0, %1, %2, %3;" : "=l"(d) : "l"(a), "l"(b), "l"(c)); return d;
}
__device__ __forceinline__ float2 up2(u64 a) {
    float2 f; asm("mov.b64 {%0, %1}, %2;" : "=f"(f.x), "=f"(f.y) : "l"(a)); return f;
}

// ---------- activations ----------
__device__ __forceinline__ float sigm(float x) {
    float e = exp2f(-1.44269504088896340736f * x);
    return __fdividef(1.0f, 1.0f + e);
}
__device__ __forceinline__ float tanh_(float x) {
    float a = fabsf(x);
    float e = exp2f(-2.88539008177792681472f * a);
    float r = __fdividef(1.0f - e, 1.0f + e);
    return copysignf(r, x);
}

// ---------- warp MMA helpers ----------
__device__ __forceinline__ uint32_t smem_u32(const void* p) {
    uint32_t a;
    asm("{ .reg .u64 t; cvta.to.shared.u64 t, %1; cvt.u32.u64 %0, t; }" : "=r"(a) : "l"(p));
    return a;
}
__device__ __forceinline__ void ldsm4(uint32_t* r, uint32_t addr) {
    asm volatile("ldmatrix.sync.aligned.m8n8.x4.shared.b16 {%0,%1,%2,%3}, [%4];"
        : "=r"(r[0]), "=r"(r[1]), "=r"(r[2]), "=r"(r[3]) : "r"(addr));
}
__device__ __forceinline__ void mma16816(float* d, const uint32_t* a, const uint32_t* b) {
    asm volatile("mma.sync.aligned.m16n8k16.row.col.f32.bf16.bf16.f32 "
        "{%0,%1,%2,%3}, {%4,%5,%6,%7}, {%8,%9}, {%0,%1,%2,%3};"
        : "+f"(d[0]), "+f"(d[1]), "+f"(d[2]), "+f"(d[3])
        : "r"(a[0]), "r"(a[1]), "r"(a[2]), "r"(a[3]), "r"(b[0]), "r"(b[1]));
}
__device__ __forceinline__ uint32_t pkbf(__nv_bfloat16 a, __nv_bfloat16 b) {
    return ((uint32_t)__bfloat16_as_ushort(b) << 16) | (uint32_t)__bfloat16_as_ushort(a);
}
__device__ __forceinline__ void split_bf(float x, __nv_bfloat16& h, __nv_bfloat16& l) {
    h = __float2bfloat16_rn(x);
    l = __float2bfloat16_rn(x - __bfloat162float(h));
}
// row/chunk -> byte offset: 144B row stride, chunk rotation mod 9
__device__ __forceinline__ uint32_t roff(int r, int c) {
    return (uint32_t)(r * 144 + ((c + (r >> 3)) % 9) * 16);
}

// ---------- K1: XZ = macro @ W_ih^T + (b_ih+b_hh); zero accumulators; mask detect ----------
__global__ void __launch_bounds__(256) k_prep(const float* __restrict__ macro,
                                              const float* __restrict__ W_ih,
                                              const float* __restrict__ b_ih,
                                              const float* __restrict__ b_hh,
                                              const unsigned char* __restrict__ masks) {
    __shared__ float xs[DM];
    int t = blockIdx.x, g = threadIdx.x;
    if (g < DM) xs[g] = macro[t * DM + g];
    if (g == 0) { g_sum[t] = 0.f; g_cnt[t] = 0.f; }
    __syncthreads();
    float acc = b_ih[g] + b_hh[g];
    const float2* wr = (const float2*)(W_ih + g * DM);
#pragma unroll 4
    for (int j = 0; j < DM / 2; j++) {
        float2 w = wr[j];
        acc = fmaf(xs[2 * j], w.x, acc);
        acc = fmaf(xs[2 * j + 1], w.y, acc);
    }
    g_XZ[t * G4 + g] = acc;

    if (blockIdx.x == 0) {
        __shared__ int s_any, s_flt;
        if (threadIdx.x == 0) { s_any = 0; s_flt = 0; }
        __syncthreads();
        int ta = 0, tf = 0;
        for (int j = threadIdx.x; j < 1024; j += 256) {
            unsigned char c1 = masks[4 * j + 1], c2 = masks[4 * j + 2], c3 = masks[4 * j + 3];
            if (c1 | c2 | c3) ta = 1;
            if (c3 == 0x3F) tf = 1;
        }
        if (ta) atomicOr(&s_any, 1);
        if (tf) atomicOr(&s_flt, 1);
        __syncthreads();
        if (threadIdx.x == 0)
            g_mask_kind = s_flt ? 2 : (s_any ? 0 : 1);
    }
}

// ---------- K2: sequential LSTM scan (single block) ----------
__global__ void __launch_bounds__(256) k_lstm(const float* __restrict__ W_hh) {
    __shared__ float h_s[H_];
    __shared__ float gact[G4];
    const int g = threadIdx.x;

    u64 w[32];
    {
        const float2* wr = (const float2*)(W_hh + g * H_);
#pragma unroll
        for (int j = 0; j < 32; j++) { float2 v = wr[j]; w[j] = pk2(v.x, v.y); }
    }
    float c = 0.f;
    if (g < H_) h_s[g] = 0.f;
    float zA = g_XZ[g];
    float zB = g_XZ[G4 + g];
    __syncthreads();

    auto do_step = [&](float zc, int t) {
        u64 a2 = pk2(0.f, 0.f);
#pragma unroll
        for (int j = 0; j < 32; j++) {
            float2 hv = ((const float2*)h_s)[j];
            a2 = ffma2(w[j], pk2(hv.x, hv.y), a2);
        }
        float2 s = up2(a2);
        float z = zc + s.x + s.y;
        float a = (g < 2 * H_ || g >= 3 * H_) ? sigm(z) : tanh_(z);
        gact[g] = a;
        __syncthreads();
        if (g < H_) {
            float iv = gact[g], fv = gact[H_ + g], gv = gact[2 * H_ + g], ov = gact[3 * H_ + g];
            c = fmaf(fv, c, iv * gv);
            float h = ov * tanh_(c);
            h_s[g] = h;
            g_hseq[t * H_ + g] = h;
        }
        __syncthreads();
    };

    for (int t = 0; t < T_; t += 2) {
        {
            float zc = zA;
            if (t + 2 < T_) zA = g_XZ[(t + 2) * G4 + g];
            do_step(zc, t);
        }
        {
            float zc = zB;
            if (t + 3 < T_) zB = g_XZ[(t + 3) * G4 + g];
            do_step(zc, t + 1);
        }
    }
}

// ---------- K3: macro1[t][o] = b1[o] + W1[o][DI:] @ h_t  (4 t per block) ----------
__global__ void __launch_bounds__(256) k_macro1(const float* __restrict__ W1,
                                                const float* __restrict__ b1) {
    __shared__ float Wm[64 * 65];
    __shared__ float hs[4 * 64];
    int t0 = blockIdx.x * 4;
    int tid = threadIdx.x;
    for (int idx = tid; idx < 64 * 64; idx += 256) {
        int o = idx >> 6, k = idx & 63;
        Wm[o * 65 + k] = W1[o * FF + DI + k];
    }
    hs[tid] = g_hseq[t0 * 64 + tid];
    __syncthreads();
    int o = tid & 63, ts = tid >> 6;
    const float* h = hs + ts * 64;
    const float* w = Wm + o * 65;
    float acc = b1[o];
#pragma unroll 8
    for (int k = 0; k < 64; k++) acc = fmaf(h[k], w[k], acc);
    g_macro1[(t0 + ts) * 64 + o] = acc;
}

// ---------- K4: warp-MMA fused MLP, persistent CTAs ----------
// smem: rows of 144B (64 bf16 data + 8 pad), chunk-rotated
#define SM_XHI 0          // 128 rows
#define SM_XLO 18432
#define SM_W1H 36864      // 64 rows
#define SM_W1L 46080
#define SM_W2H 55296
#define SM_W2L 64512
#define SM_MISC 73728
#define SMEM_MLP (SM_MISC + 1408)

template<int KC>
__device__ __forceinline__ void do_layer(
    char* sm, uint32_t sb, uint32_t aH, uint32_t aL, uint32_t bH, uint32_t bL,
    const float* initv, float acc[2][8][4],
    int wid, int lane, int a_ro, int a_co, int b_ro, int b_co)
{
    const int cpair = (lane & 3) * 2;
#pragma unroll
    for (int mi = 0; mi < 2; mi++)
#pragma unroll
        for (int ni = 0; ni < 8; ni++) {
            float v0 = initv[ni * 8 + cpair], v1 = initv[ni * 8 + cpair + 1];
            acc[mi][ni][0] = v0; acc[mi][ni][1] = v1;
            acc[mi][ni][2] = v0; acc[mi][ni][3] = v1;
        }
#pragma unroll
    for (int kc = 0; kc < KC; kc++) {
        uint32_t ah[2][4], al[2][4], bh[4][4], bl[4][4];
#pragma unroll
        for (int mi = 0; mi < 2; mi++) {
            int r = wid * 32 + mi * 16 + a_ro;
            uint32_t off = roff(r, 2 * kc + a_co);
            ldsm4(ah[mi], sb + aH + off);
            ldsm4(al[mi], sb + aL + off);
        }
#pragma unroll
        for (int np = 0; np < 4; np++) {
            int r = np * 16 + b_ro;
            uint32_t off = roff(r, 2 * kc + b_co);
            ldsm4(bh[np], sb + bH + off);
            ldsm4(bl[np], sb + bL + off);
        }
#pragma unroll
        for (int mi = 0; mi < 2; mi++)
#pragma unroll
            for (int ni = 0; ni < 8; ni++)
                mma16816(acc[mi][ni], ah[mi], &bh[ni >> 1][(ni & 1) * 2]);
#pragma unroll
        for (int mi = 0; mi < 2; mi++)
#pragma unroll
            for (int ni = 0; ni < 8; ni++)
                mma16816(acc[mi][ni], ah[mi], &bl[ni >> 1][(ni & 1) * 2]);
#pragma unroll
        for (int mi = 0; mi < 2; mi++)
#pragma unroll
            for (int ni = 0; ni < 8; ni++)
                mma16816(acc[mi][ni], al[mi], &bh[ni >> 1][(ni & 1) * 2]);
    }
}

__global__ void __launch_bounds__(128, 2)
k_mlp(const float* __restrict__ indiv, const unsigned char* __restrict__ mask_raw,
      const float* __restrict__ rets, const float* __restrict__ W1,
      const float* __restrict__ W2, const float* __restrict__ b2,
      const float* __restrict__ W3, const float* __restrict__ b3,
      float* __restrict__ out_w)
{
    extern __shared__ char sm[];
    const uint32_t sb = smem_u32(sm);
    float* m1s  = (float*)(sm + SM_MISC);
    float* b2s  = (float*)(sm + SM_MISC + 256);
    float* W3s  = (float*)(sm + SM_MISC + 512);
    float* wrow = (float*)(sm + SM_MISC + 768);
    float* red  = (float*)(sm + SM_MISC + 1280);
    float* b3s  = (float*)(sm + SM_MISC + 1344);

    const int tid = threadIdx.x;
    const int wid = tid >> 5, lane = tid & 31;
    const int lq = lane & 7, qq = lane >> 3;
    // ldmatrix lane address components
    const int a_ro = lq + ((qq & 1) << 3), a_co = qq >> 1;   // A fragments
    const int b_ro = lq + ((qq >> 1) << 3), b_co = qq & 1;   // B fragments

    // ---- one-time weight staging (hi/lo split, zero-pad K) ----
    for (int idx = tid; idx < 64 * 64; idx += 128) {
        int n = idx >> 6, k = idx & 63;
        float v1 = (k < DI) ? W1[n * FF + k] : 0.f;
        float v2 = W2[idx];
        uint32_t o = roff(n, k >> 3) + (k & 7) * 2;
        __nv_bfloat16 h, l;
        split_bf(v1, h, l);
        *(__nv_bfloat16*)(sm + SM_W1H + o) = h;
        *(__nv_bfloat16*)(sm + SM_W1L + o) = l;
        split_bf(v2, h, l);
        *(__nv_bfloat16*)(sm + SM_W2H + o) = h;
        *(__nv_bfloat16*)(sm + SM_W2L + o) = l;
    }
    if (tid < 64) { b2s[tid] = b2[tid]; W3s[tid] = W3[tid]; }
    if (tid == 0) b3s[0] = b3[0];
    __syncthreads();

    float acc[2][8][4];

    for (int tile = blockIdx.x; tile < NTILES; tile += gridDim.x) {
        const int t = tile >> 5;
        const int p0 = (tile & 31) * TILE;
        const int pg = p0 + tid;
        const bool valid = pg < NN;

        // ---- stage X row tid (own-warp rows only): chunks 0..5 (48 cols, pad 46/47) ----
        {
            const float* rp = indiv + ((size_t)t * NN + (valid ? pg : 0)) * DI;
            const uint32_t rbase = (uint32_t)(tid * 144);
            const int rot0 = tid >> 3;
#pragma unroll
            for (int c = 0; c < 6; c++) {
                float x[8];
#pragma unroll
                for (int j = 0; j < 8; j++) {
                    int col = c * 8 + j;
                    x[j] = (valid && col < DI) ? rp[col] : 0.f;
                }
                uint32_t hw[4], lw[4];
#pragma unroll
                for (int jp = 0; jp < 4; jp++) {
                    __nv_bfloat16 h0, l0, h1, l1;
                    split_bf(x[2 * jp], h0, l0);
                    split_bf(x[2 * jp + 1], h1, l1);
                    hw[jp] = pkbf(h0, h1);
                    lw[jp] = pkbf(l0, l1);
                }
                uint32_t off = rbase + (uint32_t)(((c + rot0) % 9) * 16);
                *(uint4*)(sm + SM_XHI + off) = make_uint4(hw[0], hw[1], hw[2], hw[3]);
                *(uint4*)(sm + SM_XLO + off) = make_uint4(lw[0], lw[1], lw[2], lw[3]);
            }
        }
        if (tid < 64) m1s[tid] = g_macro1[t * 64 + tid];
        __syncthreads();

        // ---- layer 1: K=48 (3 k-chunks) ----
        do_layer<3>(sm, sb, SM_XHI, SM_XLO, SM_W1H, SM_W1L, m1s, acc,
                    wid, lane, a_ro, a_co, b_ro, b_co);

        // ---- epilogue 1: relu + split, write A1 back into X buffers (own rows) ----
        __syncwarp();
#pragma unroll
        for (int mi = 0; mi < 2; mi++) {
            int R0 = wid * 32 + mi * 16 + (lane >> 2);
            int R1 = R0 + 8;
#pragma unroll
            for (int ni = 0; ni < 8; ni++) {
                float a0 = fmaxf(acc[mi][ni][0], 0.f);
                float a1 = fmaxf(acc[mi][ni][1], 0.f);
                float a2 = fmaxf(acc[mi][ni][2], 0.f);
                float a3 = fmaxf(acc[mi][ni][3], 0.f);
                __nv_bfloat16 h0, l0, h1, l1, h2, l2, h3, l3;
                split_bf(a0, h0, l0); split_bf(a1, h1, l1);
                split_bf(a2, h2, l2); split_bf(a3, h3, l3);
                uint32_t off0 = roff(R0, ni) + (lane & 3) * 4;
                uint32_t off1 = roff(R1, ni) + (lane & 3) * 4;
                *(uint32_t*)(sm + SM_XHI + off0) = pkbf(h0, h1);
                *(uint32_t*)(sm + SM_XLO + off0) = pkbf(l0, l1);
                *(uint32_t*)(sm + SM_XHI + off1) = pkbf(h2, h3);
                *(uint32_t*)(sm + SM_XLO + off1) = pkbf(l2, l3);
            }
        }
        __syncwarp();

        // ---- layer 2: K=64 (4 k-chunks) ----
        do_layer<4>(sm, sb, SM_XHI, SM_XLO, SM_W2H, SM_W2L, b2s, acc,
                    wid, lane, a_ro, a_co, b_ro, b_co);

        // ---- epilogue 2: w3 dot relu, reduce to per-point weight ----
        float ws[4] = {0.f, 0.f, 0.f, 0.f};
#pragma unroll
        for (int mi = 0; mi < 2; mi++)
#pragma unroll
            for (int ni = 0; ni < 8; ni++) {
                int col = ni * 8 + (lane & 3) * 2;
                float w0 = W3s[col], w1 = W3s[col + 1];
                ws[2 * mi]     = fmaf(w0, fmaxf(acc[mi][ni][0], 0.f),
                                 fmaf(w1, fmaxf(acc[mi][ni][1], 0.f), ws[2 * mi]));
                ws[2 * mi + 1] = fmaf(w0, fmaxf(acc[mi][ni][2], 0.f),
                                 fmaf(w1, fmaxf(acc[mi][ni][3], 0.f), ws[2 * mi + 1]));
            }
#pragma unroll
        for (int i = 0; i < 4; i++) {
            ws[i] += __shfl_xor_sync(0xffffffffu, ws[i], 1);
            ws[i] += __shfl_xor_sync(0xffffffffu, ws[i], 2);
        }
        if ((lane & 3) == 0) {
            int r = wid * 32 + (lane >> 2);
            wrow[r] = ws[0]; wrow[r + 8] = ws[1];
            wrow[r + 16] = ws[2]; wrow[r + 24] = ws[3];
        }
        __syncthreads();

        // ---- per-point finish: mask, write, accumulate ----
        float contrib = 0.f, mval = 0.f;
        {
            float w = wrow[tid] + b3s[0];
            if (valid) {
                size_t gi = (size_t)t * NN + pg;
                int kind = g_mask_kind;
                float mf = (kind == 0) ? (float)mask_raw[gi]
                         : (kind == 1) ? (float)((const int*)mask_raw)[gi]
                         : ((const float*)mask_raw)[gi];
                float wm = w * mf;
                out_w[gi] = wm;
                contrib = wm * rets[gi];
                mval = mf;
            }
        }
#pragma unroll
        for (int off = 16; off; off >>= 1) {
            contrib += __shfl_down_sync(0xffffffffu, contrib, off);
            mval    += __shfl_down_sync(0xffffffffu, mval, off);
        }
        if (lane == 0) { red[wid] = contrib; red[4 + wid] = mval; }
        __syncthreads();
        if (tid == 0) {
            atomicAdd(&g_sum[t], red[0] + red[1] + red[2] + red[3]);
            atomicAdd(&g_cnt[t], red[4] + red[5] + red[6] + red[7]);
        }
    }
}

// ---------- K5: sdf finalize ----------
__global__ void __launch_bounds__(256) k_final(float* __restrict__ out_sdf) {
    __shared__ float smr[256];
    int t = threadIdx.x;
    float cnt = g_cnt[t];
    smr[t] = cnt;
    __syncthreads();
    for (int s = 128; s > 0; s >>= 1) {
        if (t < s) smr[t] += smr[t + s];
        __syncthreads();
    }
    float mean = smr[0] * (1.0f / 256.0f);
    out_sdf[t] = g_sum[t] / cnt * mean + 1.0f;
}

// ---------- launch ----------
extern "C" void kernel_launch(void* const* d_in, const int* in_sizes, int n_in,
                              void* d_out, int out_size) {
    (void)in_sizes; (void)n_in; (void)out_size;
    const float* macro = (const float*)d_in[0];
    const float* indiv = (const float*)d_in[1];
    const unsigned char* masks = (const unsigned char*)d_in[2];
    const float* rets  = (const float*)d_in[3];
    const float* W_ih  = (const float*)d_in[4];
    const float* W_hh  = (const float*)d_in[5];
    const float* b_ih  = (const float*)d_in[6];
    const float* b_hh  = (const float*)d_in[7];
    const float* W1    = (const float*)d_in[8];
    const float* b1    = (const float*)d_in[9];
    const float* W2    = (const float*)d_in[10];
    const float* b2    = (const float*)d_in[11];
    const float* W3    = (const float*)d_in[12];
    const float* b3    = (const float*)d_in[13];

    float* out     = (float*)d_out;
    float* out_sdf = out;          // sdf [T,1]
    float* out_w   = out + T_;     // weights [1,T,N,1]

    cudaFuncSetAttribute(k_mlp, cudaFuncAttributeMaxDynamicSharedMemorySize, SMEM_MLP);

    k_prep<<<T_, G4>>>(macro, W_ih, b_ih, b_hh, masks);
    k_lstm<<<1, G4>>>(W_hh);
    k_macro1<<<T_ / 4, 256>>>(W1, b1);
    k_mlp<<<GRID_MLP, 128, SMEM_MLP>>>(indiv, masks, rets, W1, W2, b2, W3, b3, out_w);
    k_final<<<1, T_>>>(out_sdf);
}

// round 4
// speedup vs baseline: 2.4545x; 1.0431x over previous
#include <cuda_runtime.h>
#include <cuda_fp16.h>
#include <cstdint>

#define T_  256
#define NN  4000
#define DM  178
#define DI  46
#define H_  64
#define DH  64
#define FF  110   // DI + H
#define G4  256   // 4*H
#define TILE 128
#define NTILES (T_ * 32)   // 8192
#define GRID_MLP 296

typedef unsigned long long u64;

// ---------- device scratch ----------
__device__ float g_XZ[T_ * G4];
__device__ float g_hseq[T_ * H_];
__device__ float g_macro1[T_ * DH];
__device__ float g_sum[T_];
__device__ float g_cnt[T_];
__device__ int   g_mask_kind;   // 0=uint8/bool, 1=int32, 2=float32

// ---------- packed f32x2 helpers (LSTM) ----------
__device__ __forceinline__ u64 pk2(float lo, float hi) {
    u64 r; asm("mov.b64 %0, {%1, %2};" : "=l"(r) : "f"(lo), "f"(hi)); return r;
}
__device__ __forceinline__ u64 ffma2(u64 a, u64 b, u64 c) {
    u64 d; asm("fma.rn.f32x2 %0, %1, %2, %3;" : "=l"(d) : "l"(a), "l"(b), "l"(c)); return d;
}
__device__ __forceinline__ float2 up2(u64 a) {
    float2 f; asm("mov.b64 {%0, %1}, %2;" : "=f"(f.x), "=f"(f.y) : "l"(a)); return f;
}

// ---------- activations ----------
__device__ __forceinline__ float sigm(float x) {
    float e = exp2f(-1.44269504088896340736f * x);
    return __fdividef(1.0f, 1.0f + e);
}
__device__ __forceinline__ float tanh_(float x) {
    float a = fabsf(x);
    float e = exp2f(-2.88539008177792681472f * a);
    float r = __fdividef(1.0f - e, 1.0f + e);
    return copysignf(r, x);
}

// ---------- warp MMA helpers ----------
__device__ __forceinline__ uint32_t smem_u32(const void* p) {
    uint32_t a;
    asm("{ .reg .u64 t; cvta.to.shared.u64 t, %1; cvt.u32.u64 %0, t; }" : "=r"(a) : "l"(p));
    return a;
}
__device__ __forceinline__ void ldsm4(uint32_t* r, uint32_t addr) {
    asm volatile("ldmatrix.sync.aligned.m8n8.x4.shared.b16 {%0,%1,%2,%3}, [%4];"
        : "=r"(r[0]), "=r"(r[1]), "=r"(r[2]), "=r"(r[3]) : "r"(addr));
}
__device__ __forceinline__ void mma16816(float* d, const uint32_t* a, const uint32_t* b) {
    asm volatile("mma.sync.aligned.m16n8k16.row.col.f32.f16.f16.f32 "
        "{%0,%1,%2,%3}, {%4,%5,%6,%7}, {%8,%9}, {%0,%1,%2,%3};"
        : "+f"(d[0]), "+f"(d[1]), "+f"(d[2]), "+f"(d[3])
        : "r"(a[0]), "r"(a[1]), "r"(a[2]), "r"(a[3]), "r"(b[0]), "r"(b[1]));
}
__device__ __forceinline__ uint32_t pkhf(__half a, __half b) {
    return ((uint32_t)__half_as_ushort(b) << 16) | (uint32_t)__half_as_ushort(a);
}
__device__ __forceinline__ void split_hf(float x, __half& h, __half& l) {
    h = __float2half_rn(x);
    l = __float2half_rn(x - __half2float(h));
}
// row/chunk -> byte offset: 144B row stride, chunk rotation mod 9
__device__ __forceinline__ uint32_t roff(int r, int c) {
    return (uint32_t)(r * 144 + ((c + (r >> 3)) % 9) * 16);
}

// ---------- K1: XZ = macro @ W_ih^T + (b_ih+b_hh); zero accumulators; mask detect ----------
__global__ void __launch_bounds__(256) k_prep(const float* __restrict__ macro,
                                              const float* __restrict__ W_ih,
                                              const float* __restrict__ b_ih,
                                              const float* __restrict__ b_hh,
                                              const unsigned char* __restrict__ masks) {
    __shared__ float xs[DM];
    int t = blockIdx.x, g = threadIdx.x;
    if (g < DM) xs[g] = macro[t * DM + g];
    if (g == 0) { g_sum[t] = 0.f; g_cnt[t] = 0.f; }
    __syncthreads();
    float acc = b_ih[g] + b_hh[g];
    const float2* wr = (const float2*)(W_ih + g * DM);
#pragma unroll 4
    for (int j = 0; j < DM / 2; j++) {
        float2 w = wr[j];
        acc = fmaf(xs[2 * j], w.x, acc);
        acc = fmaf(xs[2 * j + 1], w.y, acc);
    }
    g_XZ[t * G4 + g] = acc;

    if (blockIdx.x == 0) {
        __shared__ int s_any, s_flt;
        if (threadIdx.x == 0) { s_any = 0; s_flt = 0; }
        __syncthreads();
        int ta = 0, tf = 0;
        for (int j = threadIdx.x; j < 1024; j += 256) {
            unsigned char c1 = masks[4 * j + 1], c2 = masks[4 * j + 2], c3 = masks[4 * j + 3];
            if (c1 | c2 | c3) ta = 1;
            if (c3 == 0x3F) tf = 1;
        }
        if (ta) atomicOr(&s_any, 1);
        if (tf) atomicOr(&s_flt, 1);
        __syncthreads();
        if (threadIdx.x == 0)
            g_mask_kind = s_flt ? 2 : (s_any ? 0 : 1);
    }
}

// ---------- K2: sequential LSTM scan (single block) ----------
__global__ void __launch_bounds__(256) k_lstm(const float* __restrict__ W_hh) {
    __shared__ float h_s[H_];
    __shared__ float gact[G4];
    const int g = threadIdx.x;

    u64 w[32];
    {
        const float2* wr = (const float2*)(W_hh + g * H_);
#pragma unroll
        for (int j = 0; j < 32; j++) { float2 v = wr[j]; w[j] = pk2(v.x, v.y); }
    }
    float c = 0.f;
    if (g < H_) h_s[g] = 0.f;
    float zA = g_XZ[g];
    float zB = g_XZ[G4 + g];
    __syncthreads();

    auto do_step = [&](float zc, int t) {
        u64 a0 = pk2(0.f, 0.f), a1 = a0, a2 = a0, a3 = a0;
#pragma unroll
        for (int j = 0; j < 32; j += 4) {
            float2 h0 = ((const float2*)h_s)[j];
            float2 h1 = ((const float2*)h_s)[j + 1];
            float2 h2 = ((const float2*)h_s)[j + 2];
            float2 h3 = ((const float2*)h_s)[j + 3];
            a0 = ffma2(w[j],     pk2(h0.x, h0.y), a0);
            a1 = ffma2(w[j + 1], pk2(h1.x, h1.y), a1);
            a2 = ffma2(w[j + 2], pk2(h2.x, h2.y), a2);
            a3 = ffma2(w[j + 3], pk2(h3.x, h3.y), a3);
        }
        a0 = ffma2(pk2(1.f, 1.f), a1, a0);
        a2 = ffma2(pk2(1.f, 1.f), a3, a2);
        float2 s0 = up2(a0), s2 = up2(a2);
        float z = zc + ((s0.x + s0.y) + (s2.x + s2.y));
        float a = (g < 2 * H_ || g >= 3 * H_) ? sigm(z) : tanh_(z);
        gact[g] = a;
        __syncthreads();
        if (g < H_) {
            float iv = gact[g], fv = gact[H_ + g], gv = gact[2 * H_ + g], ov = gact[3 * H_ + g];
            c = fmaf(fv, c, iv * gv);
            float h = ov * tanh_(c);
            h_s[g] = h;
            g_hseq[t * H_ + g] = h;
        }
        __syncthreads();
    };

    for (int t = 0; t < T_; t += 2) {
        {
            float zc = zA;
            if (t + 2 < T_) zA = g_XZ[(t + 2) * G4 + g];
            do_step(zc, t);
        }
        {
            float zc = zB;
            if (t + 3 < T_) zB = g_XZ[(t + 3) * G4 + g];
            do_step(zc, t + 1);
        }
    }
}

// ---------- K3: macro1[t][o] = b1[o] + W1[o][DI:] @ h_t  (4 t per block) ----------
__global__ void __launch_bounds__(256) k_macro1(const float* __restrict__ W1,
                                                const float* __restrict__ b1) {
    __shared__ float Wm[64 * 65];
    __shared__ float hs[4 * 64];
    int t0 = blockIdx.x * 4;
    int tid = threadIdx.x;
    for (int idx = tid; idx < 64 * 64; idx += 256) {
        int o = idx >> 6, k = idx & 63;
        Wm[o * 65 + k] = W1[o * FF + DI + k];
    }
    hs[tid] = g_hseq[t0 * 64 + tid];
    __syncthreads();
    int o = tid & 63, ts = tid >> 6;
    const float* h = hs + ts * 64;
    const float* w = Wm + o * 65;
    float acc = b1[o];
#pragma unroll 8
    for (int k = 0; k < 64; k++) acc = fmaf(h[k], w[k], acc);
    g_macro1[(t0 + ts) * 64 + o] = acc;
}

// ---------- K4: warp-MMA fused MLP (fp16 2-term split), persistent CTAs ----------
#define SM_XHI 0          // 128 rows x 144B
#define SM_XLO 18432
#define SM_W1H 36864      // 64 rows x 144B
#define SM_W2H 46080
#define SM_RAW 55296      // 128 x 184B raw X staging
#define SM_MISC 78848
#define SMEM_MLP (SM_MISC + 1408)

template<int KC>
__device__ __forceinline__ void do_layer(
    char* sm, uint32_t sb, uint32_t aH, uint32_t aL, uint32_t bH,
    const float* initv, float acc[2][8][4],
    int wid, int lane, int a_ro, int a_co, int b_ro, int b_co)
{
    const int cpair = (lane & 3) * 2;
#pragma unroll
    for (int mi = 0; mi < 2; mi++)
#pragma unroll
        for (int ni = 0; ni < 8; ni++) {
            float v0 = initv[ni * 8 + cpair], v1 = initv[ni * 8 + cpair + 1];
            acc[mi][ni][0] = v0; acc[mi][ni][1] = v1;
            acc[mi][ni][2] = v0; acc[mi][ni][3] = v1;
        }
#pragma unroll
    for (int kc = 0; kc < KC; kc++) {
        uint32_t ah[2][4], al[2][4], bh[4][4];
#pragma unroll
        for (int mi = 0; mi < 2; mi++) {
            int r = wid * 32 + mi * 16 + a_ro;
            uint32_t off = roff(r, 2 * kc + a_co);
            ldsm4(ah[mi], sb + aH + off);
            ldsm4(al[mi], sb + aL + off);
        }
#pragma unroll
        for (int np = 0; np < 4; np++) {
            int r = np * 16 + b_ro;
            uint32_t off = roff(r, 2 * kc + b_co);
            ldsm4(bh[np], sb + bH + off);
        }
#pragma unroll
        for (int mi = 0; mi < 2; mi++)
#pragma unroll
            for (int ni = 0; ni < 8; ni++)
                mma16816(acc[mi][ni], ah[mi], &bh[ni >> 1][(ni & 1) * 2]);
#pragma unroll
        for (int mi = 0; mi < 2; mi++)
#pragma unroll
            for (int ni = 0; ni < 8; ni++)
                mma16816(acc[mi][ni], al[mi], &bh[ni >> 1][(ni & 1) * 2]);
    }
}

__global__ void __launch_bounds__(128, 2)
k_mlp(const float* __restrict__ indiv, const unsigned char* __restrict__ mask_raw,
      const float* __restrict__ rets, const float* __restrict__ W1,
      const float* __restrict__ W2, const float* __restrict__ b2,
      const float* __restrict__ W3, const float* __restrict__ b3,
      float* __restrict__ out_w)
{
    extern __shared__ char sm[];
    const uint32_t sb = smem_u32(sm);
    float* m1s  = (float*)(sm + SM_MISC);
    float* b2s  = (float*)(sm + SM_MISC + 256);
    float* W3s  = (float*)(sm + SM_MISC + 512);
    float* wrow = (float*)(sm + SM_MISC + 768);
    float* red  = (float*)(sm + SM_MISC + 1280);
    float* b3s  = (float*)(sm + SM_MISC + 1344);
    float* rawf = (float*)(sm + SM_RAW);

    const int tid = threadIdx.x;
    const int wid = tid >> 5, lane = tid & 31;
    const int lq = lane & 7, qq = lane >> 3;
    const int a_ro = lq + ((qq & 1) << 3), a_co = qq >> 1;
    const int b_ro = lq + ((qq >> 1) << 3), b_co = qq & 1;

    // ---- one-time weight staging (fp16 hi only, zero-pad K) ----
    for (int idx = tid; idx < 64 * 64; idx += 128) {
        int n = idx >> 6, k = idx & 63;
        float v1 = (k < DI) ? W1[n * FF + k] : 0.f;
        float v2 = W2[idx];
        uint32_t o = roff(n, k >> 3) + (k & 7) * 2;
        *(__half*)(sm + SM_W1H + o) = __float2half_rn(v1);
        *(__half*)(sm + SM_W2H + o) = __float2half_rn(v2);
    }
    if (tid < 64) { b2s[tid] = b2[tid]; W3s[tid] = W3[tid]; }
    if (tid == 0) b3s[0] = b3[0];
    __syncthreads();

    float acc[2][8][4];

    for (int tile = blockIdx.x; tile < NTILES; tile += gridDim.x) {
        const int t = tile >> 5;
        const int p0 = (tile & 31) * TILE;
        const int pg = p0 + tid;
        const bool valid = pg < NN;
        const int vrows = min(TILE, NN - p0);

        // ---- phase 1: coalesced raw copy of X block into smem ----
        {
            const float4* gsrc = (const float4*)(indiv + ((size_t)t * NN + p0) * DI);
            float4* dst = (float4*)rawf;
            const int n4 = vrows * DI / 4;   // vrows*46 divisible by 4 for vrows in {128,32}
            for (int i = tid; i < n4; i += 128) dst[i] = gsrc[i];
        }
        if (tid < 64) m1s[tid] = g_macro1[t * 64 + tid];
        __syncthreads();

        // ---- phase 2: split own row to fp16 hi/lo, swizzled STS ----
        {
            const float* rp = rawf + tid * DI;
            const uint32_t rbase = (uint32_t)(tid * 144);
            const int rot0 = tid >> 3;
#pragma unroll
            for (int c = 0; c < 6; c++) {
                uint32_t hw[4], lw[4];
#pragma unroll
                for (int jp = 0; jp < 4; jp++) {
                    int c0 = c * 8 + 2 * jp, c1 = c0 + 1;
                    float x0 = (valid && c0 < DI) ? rp[c0] : 0.f;
                    float x1 = (valid && c1 < DI) ? rp[c1] : 0.f;
                    __half h0, l0, h1, l1;
                    split_hf(x0, h0, l0);
                    split_hf(x1, h1, l1);
                    hw[jp] = pkhf(h0, h1);
                    lw[jp] = pkhf(l0, l1);
                }
                uint32_t off = rbase + (uint32_t)(((c + rot0) % 9) * 16);
                *(uint4*)(sm + SM_XHI + off) = make_uint4(hw[0], hw[1], hw[2], hw[3]);
                *(uint4*)(sm + SM_XLO + off) = make_uint4(lw[0], lw[1], lw[2], lw[3]);
            }
        }
        __syncthreads();

        // ---- layer 1: K=48 (3 k-chunks), 2-term ----
        do_layer<3>(sm, sb, SM_XHI, SM_XLO, SM_W1H, m1s, acc,
                    wid, lane, a_ro, a_co, b_ro, b_co);

        // ---- epilogue 1: relu + split, write A1 back (own-warp rows) ----
        __syncwarp();
#pragma unroll
        for (int mi = 0; mi < 2; mi++) {
            int R0 = wid * 32 + mi * 16 + (lane >> 2);
            int R1 = R0 + 8;
#pragma unroll
            for (int ni = 0; ni < 8; ni++) {
                float a0 = fmaxf(acc[mi][ni][0], 0.f);
                float a1 = fmaxf(acc[mi][ni][1], 0.f);
                float a2 = fmaxf(acc[mi][ni][2], 0.f);
                float a3 = fmaxf(acc[mi][ni][3], 0.f);
                __half h0, l0, h1, l1, h2, l2, h3, l3;
                split_hf(a0, h0, l0); split_hf(a1, h1, l1);
                split_hf(a2, h2, l2); split_hf(a3, h3, l3);
                uint32_t off0 = roff(R0, ni) + (lane & 3) * 4;
                uint32_t off1 = roff(R1, ni) + (lane & 3) * 4;
                *(uint32_t*)(sm + SM_XHI + off0) = pkhf(h0, h1);
                *(uint32_t*)(sm + SM_XLO + off0) = pkhf(l0, l1);
                *(uint32_t*)(sm + SM_XHI + off1) = pkhf(h2, h3);
                *(uint32_t*)(sm + SM_XLO + off1) = pkhf(l2, l3);
            }
        }
        __syncwarp();

        // ---- layer 2: K=64 (4 k-chunks), 2-term ----
        do_layer<4>(sm, sb, SM_XHI, SM_XLO, SM_W2H, b2s, acc,
                    wid, lane, a_ro, a_co, b_ro, b_co);

        // ---- epilogue 2: w3 dot relu, reduce to per-point weight ----
        float ws[4] = {0.f, 0.f, 0.f, 0.f};
#pragma unroll
        for (int mi = 0; mi < 2; mi++)
#pragma unroll
            for (int ni = 0; ni < 8; ni++) {
                int col = ni * 8 + (lane & 3) * 2;
                float w0 = W3s[col], w1 = W3s[col + 1];
                ws[2 * mi]     = fmaf(w0, fmaxf(acc[mi][ni][0], 0.f),
                                 fmaf(w1, fmaxf(acc[mi][ni][1], 0.f), ws[2 * mi]));
                ws[2 * mi + 1] = fmaf(w0, fmaxf(acc[mi][ni][2], 0.f),
                                 fmaf(w1, fmaxf(acc[mi][ni][3], 0.f), ws[2 * mi + 1]));
            }
#pragma unroll
        for (int i = 0; i < 4; i++) {
            ws[i] += __shfl_xor_sync(0xffffffffu, ws[i], 1);
            ws[i] += __shfl_xor_sync(0xffffffffu, ws[i], 2);
        }
        if ((lane & 3) == 0) {
            int r = wid * 32 + (lane >> 2);
            wrow[r] = ws[0]; wrow[r + 8] = ws[1];
            wrow[r + 16] = ws[2]; wrow[r + 24] = ws[3];
        }
        __syncthreads();

        // ---- per-point finish: mask, write, accumulate ----
        float contrib = 0.f, mval = 0.f;
        {
            float w = wrow[tid] + b3s[0];
            if (valid) {
                size_t gi = (size_t)t * NN + pg;
                int kind = g_mask_kind;
                float mf = (kind == 0) ? (float)mask_raw[gi]
                         : (kind == 1) ? (float)((const int*)mask_raw)[gi]
                         : ((const float*)mask_raw)[gi];
                float wm = w * mf;
                out_w[gi] = wm;
                contrib = wm * rets[gi];
                mval = mf;
            }
        }
#pragma unroll
        for (int off = 16; off; off >>= 1) {
            contrib += __shfl_down_sync(0xffffffffu, contrib, off);
            mval    += __shfl_down_sync(0xffffffffu, mval, off);
        }
        if (lane == 0) { red[wid] = contrib; red[4 + wid] = mval; }
        __syncthreads();
        if (tid == 0) {
            atomicAdd(&g_sum[t], red[0] + red[1] + red[2] + red[3]);
            atomicAdd(&g_cnt[t], red[4] + red[5] + red[6] + red[7]);
        }
    }
}

// ---------- K5: sdf finalize ----------
__global__ void __launch_bounds__(256) k_final(float* __restrict__ out_sdf) {
    __shared__ float smr[256];
    int t = threadIdx.x;
    float cnt = g_cnt[t];
    smr[t] = cnt;
    __syncthreads();
    for (int s = 128; s > 0; s >>= 1) {
        if (t < s) smr[t] += smr[t + s];
        __syncthreads();
    }
    float mean = smr[0] * (1.0f / 256.0f);
    out_sdf[t] = g_sum[t] / cnt * mean + 1.0f;
}

// ---------- launch ----------
extern "C" void kernel_launch(void* const* d_in, const int* in_sizes, int n_in,
                              void* d_out, int out_size) {
    (void)in_sizes; (void)n_in; (void)out_size;
    const float* macro = (const float*)d_in[0];
    const float* indiv = (const float*)d_in[1];
    const unsigned char* masks = (const unsigned char*)d_in[2];
    const float* rets  = (const float*)d_in[3];
    const float* W_ih  = (const float*)d_in[4];
    const float* W_hh  = (const float*)d_in[5];
    const float* b_ih  = (const float*)d_in[6];
    const float* b_hh  = (const float*)d_in[7];
    const float* W1    = (const float*)d_in[8];
    const float* b1    = (const float*)d_in[9];
    const float* W2    = (const float*)d_in[10];
    const float* b2    = (const float*)d_in[11];
    const float* W3    = (const float*)d_in[12];
    const float* b3    = (const float*)d_in[13];

    float* out     = (float*)d_out;
    float* out_sdf = out;          // sdf [T,1]
    float* out_w   = out + T_;     // weights [1,T,N,1]

    cudaFuncSetAttribute(k_mlp, cudaFuncAttributeMaxDynamicSharedMemorySize, SMEM_MLP);

    k_prep<<<T_, G4>>>(macro, W_ih, b_ih, b_hh, masks);
    k_lstm<<<1, G4>>>(W_hh);
    k_macro1<<<T_ / 4, 256>>>(W1, b1);
    k_mlp<<<GRID_MLP, 128, SMEM_MLP>>>(indiv, masks, rets, W1, W2, b2, W3, b3, out_w);
    k_final<<<1, T_>>>(out_sdf);
}

// round 5
// speedup vs baseline: 2.6119x; 1.0641x over previous
#include <cuda_runtime.h>
#include <cuda_fp16.h>
#include <cstdint>

#define T_  256
#define NN  4000
#define DM  178
#define DI  46
#define H_  64
#define DH  64
#define FF  110   // DI + H
#define G4  256   // 4*H
#define TILE 128
#define NTILES (T_ * 32)   // 8192
#define GRID_MLP 296

typedef unsigned long long u64;

// ---------- device scratch ----------
__device__ float g_XZ[T_ * G4];
__device__ float g_hseq[T_ * H_];
__device__ float g_macro1[T_ * DH];
__device__ float g_sum[T_];
__device__ float g_cnt[T_];
__device__ int   g_mask_kind;   // 0=uint8/bool, 1=int32, 2=float32

// ---------- packed f32x2 helpers (LSTM) ----------
__device__ __forceinline__ u64 pk2(float lo, float hi) {
    u64 r; asm("mov.b64 %0, {%1, %2};" : "=l"(r) : "f"(lo), "f"(hi)); return r;
}
__device__ __forceinline__ u64 ffma2(u64 a, u64 b, u64 c) {
    u64 d; asm("fma.rn.f32x2 %0, %1, %2, %3;" : "=l"(d) : "l"(a), "l"(b), "l"(c)); return d;
}
__device__ __forceinline__ float2 up2(u64 a) {
    float2 f; asm("mov.b64 {%0, %1}, %2;" : "=f"(f.x), "=f"(f.y) : "l"(a)); return f;
}

// ---------- activations ----------
__device__ __forceinline__ float sigm(float x) {
    float e = exp2f(-1.44269504088896340736f * x);
    return __fdividef(1.0f, 1.0f + e);
}
__device__ __forceinline__ float tanh_(float x) {
    float a = fabsf(x);
    float e = exp2f(-2.88539008177792681472f * a);
    float r = __fdividef(1.0f - e, 1.0f + e);
    return copysignf(r, x);
}

// ---------- warp MMA helpers ----------
__device__ __forceinline__ uint32_t smem_u32(const void* p) {
    uint32_t a;
    asm("{ .reg .u64 t; cvta.to.shared.u64 t, %1; cvt.u32.u64 %0, t; }" : "=r"(a) : "l"(p));
    return a;
}
__device__ __forceinline__ void ldsm4(uint32_t* r, uint32_t addr) {
    asm volatile("ldmatrix.sync.aligned.m8n8.x4.shared.b16 {%0,%1,%2,%3}, [%4];"
        : "=r"(r[0]), "=r"(r[1]), "=r"(r[2]), "=r"(r[3]) : "r"(addr));
}
__device__ __forceinline__ void mma16816(float* d, const uint32_t* a, const uint32_t* b) {
    asm volatile("mma.sync.aligned.m16n8k16.row.col.f32.f16.f16.f32 "
        "{%0,%1,%2,%3}, {%4,%5,%6,%7}, {%8,%9}, {%0,%1,%2,%3};"
        : "+f"(d[0]), "+f"(d[1]), "+f"(d[2]), "+f"(d[3])
        : "r"(a[0]), "r"(a[1]), "r"(a[2]), "r"(a[3]), "r"(b[0]), "r"(b[1]));
}
__device__ __forceinline__ uint32_t pkhf(__half a, __half b) {
    return ((uint32_t)__half_as_ushort(b) << 16) | (uint32_t)__half_as_ushort(a);
}
__device__ __forceinline__ void split_hf(float x, __half& h, __half& l) {
    h = __float2half_rn(x);
    l = __float2half_rn(x - __half2float(h));
}
// row/chunk -> byte offset: 144B row stride, chunk rotation mod 9
__device__ __forceinline__ uint32_t roff(int r, int c) {
    return (uint32_t)(r * 144 + ((c + (r >> 3)) % 9) * 16);
}
__device__ __forceinline__ void cp16(uint32_t saddr, const void* gaddr) {
    asm volatile("cp.async.cg.shared.global [%0], [%1], 16;" :: "r"(saddr), "l"(gaddr));
}

// ---------- K1: XZ = macro @ W_ih^T + (b_ih+b_hh); zero accumulators; mask detect ----------
__global__ void __launch_bounds__(256) k_prep(const float* __restrict__ macro,
                                              const float* __restrict__ W_ih,
                                              const float* __restrict__ b_ih,
                                              const float* __restrict__ b_hh,
                                              const unsigned char* __restrict__ masks) {
    __shared__ float xs[DM];
    int t = blockIdx.x, g = threadIdx.x;
    if (g < DM) xs[g] = macro[t * DM + g];
    if (g == 0) { g_sum[t] = 0.f; g_cnt[t] = 0.f; }
    __syncthreads();
    float acc = b_ih[g] + b_hh[g];
    const float2* wr = (const float2*)(W_ih + g * DM);
#pragma unroll 4
    for (int j = 0; j < DM / 2; j++) {
        float2 w = wr[j];
        acc = fmaf(xs[2 * j], w.x, acc);
        acc = fmaf(xs[2 * j + 1], w.y, acc);
    }
    g_XZ[t * G4 + g] = acc;

    if (blockIdx.x == 0) {
        __shared__ int s_any, s_flt;
        if (threadIdx.x == 0) { s_any = 0; s_flt = 0; }
        __syncthreads();
        int ta = 0, tf = 0;
        for (int j = threadIdx.x; j < 1024; j += 256) {
            unsigned char c1 = masks[4 * j + 1], c2 = masks[4 * j + 2], c3 = masks[4 * j + 3];
            if (c1 | c2 | c3) ta = 1;
            if (c3 == 0x3F) tf = 1;
        }
        if (ta) atomicOr(&s_any, 1);
        if (tf) atomicOr(&s_flt, 1);
        __syncthreads();
        if (threadIdx.x == 0)
            g_mask_kind = s_flt ? 2 : (s_any ? 0 : 1);
    }
}

// ---------- K2: sequential LSTM scan (single block) ----------
__global__ void __launch_bounds__(256) k_lstm(const float* __restrict__ W_hh) {
    __shared__ float h_s[H_];
    __shared__ float gact[G4];
    const int g = threadIdx.x;

    u64 w[32];
    {
        const float2* wr = (const float2*)(W_hh + g * H_);
#pragma unroll
        for (int j = 0; j < 32; j++) { float2 v = wr[j]; w[j] = pk2(v.x, v.y); }
    }
    float c = 0.f;
    if (g < H_) h_s[g] = 0.f;
    float zA = g_XZ[g];
    float zB = g_XZ[G4 + g];
    __syncthreads();

    auto do_step = [&](float zc, int t) {
        u64 a0 = pk2(0.f, 0.f), a1 = a0, a2 = a0, a3 = a0;
#pragma unroll
        for (int j = 0; j < 32; j += 4) {
            float2 h0 = ((const float2*)h_s)[j];
            float2 h1 = ((const float2*)h_s)[j + 1];
            float2 h2 = ((const float2*)h_s)[j + 2];
            float2 h3 = ((const float2*)h_s)[j + 3];
            a0 = ffma2(w[j],     pk2(h0.x, h0.y), a0);
            a1 = ffma2(w[j + 1], pk2(h1.x, h1.y), a1);
            a2 = ffma2(w[j + 2], pk2(h2.x, h2.y), a2);
            a3 = ffma2(w[j + 3], pk2(h3.x, h3.y), a3);
        }
        a0 = ffma2(pk2(1.f, 1.f), a1, a0);
        a2 = ffma2(pk2(1.f, 1.f), a3, a2);
        float2 s0 = up2(a0), s2 = up2(a2);
        float z = zc + ((s0.x + s0.y) + (s2.x + s2.y));
        float a = (g < 2 * H_ || g >= 3 * H_) ? sigm(z) : tanh_(z);
        gact[g] = a;
        __syncthreads();
        if (g < H_) {
            float iv = gact[g], fv = gact[H_ + g], gv = gact[2 * H_ + g], ov = gact[3 * H_ + g];
            c = fmaf(fv, c, iv * gv);
            float h = ov * tanh_(c);
            h_s[g] = h;
            g_hseq[t * H_ + g] = h;
        }
        __syncthreads();
    };

    for (int t = 0; t < T_; t += 2) {
        {
            float zc = zA;
            if (t + 2 < T_) zA = g_XZ[(t + 2) * G4 + g];
            do_step(zc, t);
        }
        {
            float zc = zB;
            if (t + 3 < T_) zB = g_XZ[(t + 3) * G4 + g];
            do_step(zc, t + 1);
        }
    }
}

// ---------- K3: macro1[t][o] = b1[o] + W1[o][DI:] @ h_t  (4 t per block) ----------
__global__ void __launch_bounds__(256) k_macro1(const float* __restrict__ W1,
                                                const float* __restrict__ b1) {
    __shared__ float Wm[64 * 65];
    __shared__ float hs[4 * 64];
    int t0 = blockIdx.x * 4;
    int tid = threadIdx.x;
    for (int idx = tid; idx < 64 * 64; idx += 256) {
        int o = idx >> 6, k = idx & 63;
        Wm[o * 65 + k] = W1[o * FF + DI + k];
    }
    hs[tid] = g_hseq[t0 * 64 + tid];
    __syncthreads();
    int o = tid & 63, ts = tid >> 6;
    const float* h = hs + ts * 64;
    const float* w = Wm + o * 65;
    float acc = b1[o];
#pragma unroll 8
    for (int k = 0; k < 64; k++) acc = fmaf(h[k], w[k], acc);
    g_macro1[(t0 + ts) * 64 + o] = acc;
}

// ---------- K4: warp-MMA fused MLP, per-warp independent pipelines ----------
// smem: XHI/XLO 128x144B, W1H/W1L/W2H/W2L 64x144B, RAW 4x(32x184B), WROW 128 floats
#define SM_XHI 0
#define SM_XLO 18432
#define SM_W1H 36864
#define SM_W1L 46080
#define SM_W2H 55296
#define SM_W2L 64512
#define SM_RAW 73728      // 4 warp slabs x 5888B
#define SM_WROW (SM_RAW + 23552)
#define SMEM_MLP (SM_WROW + 512)

// one layer: 3-term fp16 split (ah*bh + al*bh + ah*bl)
template<int KC>
__device__ __forceinline__ void do_layer(
    char* sm, uint32_t sb, uint32_t aH, uint32_t aL, uint32_t bH, uint32_t bL,
    const float* iv, float acc[2][8][4],
    int wid, int lane, int a_ro, int a_co, int b_ro, int b_co)
{
#pragma unroll
    for (int mi = 0; mi < 2; mi++)
#pragma unroll
        for (int ni = 0; ni < 8; ni++) {
            acc[mi][ni][0] = iv[2 * ni];
            acc[mi][ni][1] = iv[2 * ni + 1];
            acc[mi][ni][2] = iv[2 * ni];
            acc[mi][ni][3] = iv[2 * ni + 1];
        }
#pragma unroll
    for (int kc = 0; kc < KC; kc++) {
        uint32_t ah[2][4], al[2][4], bh[4][4], bl[4][4];
#pragma unroll
        for (int mi = 0; mi < 2; mi++) {
            int r = wid * 32 + mi * 16 + a_ro;
            uint32_t off = roff(r, 2 * kc + a_co);
            ldsm4(ah[mi], sb + aH + off);
            ldsm4(al[mi], sb + aL + off);
        }
#pragma unroll
        for (int np = 0; np < 4; np++) {
            int r = np * 16 + b_ro;
            uint32_t off = roff(r, 2 * kc + b_co);
            ldsm4(bh[np], sb + bH + off);
            ldsm4(bl[np], sb + bL + off);
        }
#pragma unroll
        for (int mi = 0; mi < 2; mi++)
#pragma unroll
            for (int ni = 0; ni < 8; ni++)
                mma16816(acc[mi][ni], ah[mi], &bh[ni >> 1][(ni & 1) * 2]);
#pragma unroll
        for (int mi = 0; mi < 2; mi++)
#pragma unroll
            for (int ni = 0; ni < 8; ni++)
                mma16816(acc[mi][ni], al[mi], &bh[ni >> 1][(ni & 1) * 2]);
#pragma unroll
        for (int mi = 0; mi < 2; mi++)
#pragma unroll
            for (int ni = 0; ni < 8; ni++)
                mma16816(acc[mi][ni], ah[mi], &bl[ni >> 1][(ni & 1) * 2]);
    }
}

__global__ void __launch_bounds__(128, 2)
k_mlp(const float* __restrict__ indiv, const unsigned char* __restrict__ mask_raw,
      const float* __restrict__ rets, const float* __restrict__ W1,
      const float* __restrict__ W2, const float* __restrict__ b2,
      const float* __restrict__ W3, const float* __restrict__ b3,
      float* __restrict__ out_w)
{
    extern __shared__ char sm[];
    const uint32_t sb = smem_u32(sm);
    float* wrow = (float*)(sm + SM_WROW);

    const int tid = threadIdx.x;
    const int wid = tid >> 5, lane = tid & 31;
    const int lq = lane & 7, qq = lane >> 3;
    const int a_ro = lq + ((qq & 1) << 3), a_co = qq >> 1;
    const int b_ro = lq + ((qq >> 1) << 3), b_co = qq & 1;
    const int cpair = (lane & 3) * 2;

    // ---- one-time weight staging (fp16 hi/lo, zero-pad K) ----
    for (int idx = tid; idx < 64 * 64; idx += 128) {
        int n = idx >> 6, k = idx & 63;
        float v1 = (k < DI) ? W1[n * FF + k] : 0.f;
        float v2 = W2[idx];
        uint32_t o = roff(n, k >> 3) + (k & 7) * 2;
        __half h, l;
        split_hf(v1, h, l);
        *(__half*)(sm + SM_W1H + o) = h;
        *(__half*)(sm + SM_W1L + o) = l;
        split_hf(v2, h, l);
        *(__half*)(sm + SM_W2H + o) = h;
        *(__half*)(sm + SM_W2L + o) = l;
    }
    // per-thread loop-invariant vectors
    float b2v[16], w3v[16];
#pragma unroll
    for (int ni = 0; ni < 8; ni++) {
        b2v[2 * ni]     = b2[ni * 8 + cpair];
        b2v[2 * ni + 1] = b2[ni * 8 + cpair + 1];
        w3v[2 * ni]     = W3[ni * 8 + cpair];
        w3v[2 * ni + 1] = W3[ni * 8 + cpair + 1];
    }
    const float b3v = b3[0];
    const int mask_kind = g_mask_kind;   // set by k_prep (prior kernel)
    __syncthreads();   // weights visible to all warps; last block-wide sync

    float acc[2][8][4];
    const uint32_t slab = sb + SM_RAW + wid * 5888;
    const float* rawf = (const float*)(sm + SM_RAW + wid * 5888);

    for (int tile = blockIdx.x; tile < NTILES; tile += gridDim.x) {
        const int t = tile >> 5;
        const int p0 = (tile & 31) * TILE;
        const int pg = p0 + tid;
        const bool valid = pg < NN;
        const bool wvalid = (p0 + wid * 32) < NN;   // warp-slab aligned with NN boundary

        // ---- per-warp cp.async staging of own 32 rows (368 x 16B) ----
        if (wvalid) {
            const float4* gsrc = (const float4*)(indiv + ((size_t)t * NN + p0 + wid * 32) * DI);
#pragma unroll
            for (int i = lane; i < 368; i += 32)
                cp16(slab + (uint32_t)i * 16, gsrc + i);
            asm volatile("cp.async.commit_group;" ::: "memory");
            asm volatile("cp.async.wait_group 0;" ::: "memory");
        }
        // per-tile macro1 init values (L1-cached)
        float m1v[16];
#pragma unroll
        for (int ni = 0; ni < 8; ni++) {
            m1v[2 * ni]     = __ldg(&g_macro1[t * 64 + ni * 8 + cpair]);
            m1v[2 * ni + 1] = __ldg(&g_macro1[t * 64 + ni * 8 + cpair + 1]);
        }
        __syncwarp();

        // ---- split own row to fp16 hi/lo, swizzled STS ----
        {
            const float* rp = rawf + lane * DI;
            const uint32_t rbase = (uint32_t)(tid * 144);
            const int rot0 = tid >> 3;
#pragma unroll
            for (int c = 0; c < 6; c++) {
                uint32_t hw[4], lw[4];
#pragma unroll
                for (int jp = 0; jp < 4; jp++) {
                    int c0 = c * 8 + 2 * jp, c1 = c0 + 1;
                    float x0 = (valid && c0 < DI) ? rp[c0] : 0.f;
                    float x1 = (valid && c1 < DI) ? rp[c1] : 0.f;
                    __half h0, l0, h1, l1;
                    split_hf(x0, h0, l0);
                    split_hf(x1, h1, l1);
                    hw[jp] = pkhf(h0, h1);
                    lw[jp] = pkhf(l0, l1);
                }
                uint32_t off = rbase + (uint32_t)(((c + rot0) % 9) * 16);
                *(uint4*)(sm + SM_XHI + off) = make_uint4(hw[0], hw[1], hw[2], hw[3]);
                *(uint4*)(sm + SM_XLO + off) = make_uint4(lw[0], lw[1], lw[2], lw[3]);
            }
        }
        __syncwarp();

        // ---- layer 1: K=48 (3 k-chunks) ----
        do_layer<3>(sm, sb, SM_XHI, SM_XLO, SM_W1H, SM_W1L, m1v, acc,
                    wid, lane, a_ro, a_co, b_ro, b_co);

        // ---- epilogue 1: relu + split, write A1 back (own-warp rows) ----
        __syncwarp();
#pragma unroll
        for (int mi = 0; mi < 2; mi++) {
            int R0 = wid * 32 + mi * 16 + (lane >> 2);
            int R1 = R0 + 8;
#pragma unroll
            for (int ni = 0; ni < 8; ni++) {
                float a0 = fmaxf(acc[mi][ni][0], 0.f);
                float a1 = fmaxf(acc[mi][ni][1], 0.f);
                float a2 = fmaxf(acc[mi][ni][2], 0.f);
                float a3 = fmaxf(acc[mi][ni][3], 0.f);
                __half h0, l0, h1, l1, h2, l2, h3, l3;
                split_hf(a0, h0, l0); split_hf(a1, h1, l1);
                split_hf(a2, h2, l2); split_hf(a3, h3, l3);
                uint32_t off0 = roff(R0, ni) + (lane & 3) * 4;
                uint32_t off1 = roff(R1, ni) + (lane & 3) * 4;
                *(uint32_t*)(sm + SM_XHI + off0) = pkhf(h0, h1);
                *(uint32_t*)(sm + SM_XLO + off0) = pkhf(l0, l1);
                *(uint32_t*)(sm + SM_XHI + off1) = pkhf(h2, h3);
                *(uint32_t*)(sm + SM_XLO + off1) = pkhf(l2, l3);
            }
        }
        __syncwarp();

        // ---- layer 2: K=64 (4 k-chunks) ----
        do_layer<4>(sm, sb, SM_XHI, SM_XLO, SM_W2H, SM_W2L, b2v, acc,
                    wid, lane, a_ro, a_co, b_ro, b_co);

        // ---- epilogue 2: w3 dot relu -> per-row weight (own warp rows) ----
        float ws[4] = {0.f, 0.f, 0.f, 0.f};
#pragma unroll
        for (int mi = 0; mi < 2; mi++)
#pragma unroll
            for (int ni = 0; ni < 8; ni++) {
                ws[2 * mi]     = fmaf(w3v[2 * ni], fmaxf(acc[mi][ni][0], 0.f),
                                 fmaf(w3v[2 * ni + 1], fmaxf(acc[mi][ni][1], 0.f), ws[2 * mi]));
                ws[2 * mi + 1] = fmaf(w3v[2 * ni], fmaxf(acc[mi][ni][2], 0.f),
                                 fmaf(w3v[2 * ni + 1], fmaxf(acc[mi][ni][3], 0.f), ws[2 * mi + 1]));
            }
#pragma unroll
        for (int i = 0; i < 4; i++) {
            ws[i] += __shfl_xor_sync(0xffffffffu, ws[i], 1);
            ws[i] += __shfl_xor_sync(0xffffffffu, ws[i], 2);
        }
        if ((lane & 3) == 0) {
            int r = wid * 32 + (lane >> 2);
            wrow[r] = ws[0]; wrow[r + 8] = ws[1];
            wrow[r + 16] = ws[2]; wrow[r + 24] = ws[3];
        }
        __syncwarp();

        // ---- per-point finish: mask, write, warp-reduce, atomic ----
        float contrib = 0.f, mval = 0.f;
        {
            float w = wrow[tid] + b3v;
            if (valid) {
                size_t gi = (size_t)t * NN + pg;
                float mf = (mask_kind == 0) ? (float)mask_raw[gi]
                         : (mask_kind == 1) ? (float)((const int*)mask_raw)[gi]
                         : ((const float*)mask_raw)[gi];
                float wm = w * mf;
                out_w[gi] = wm;
                contrib = wm * rets[gi];
                mval = mf;
            }
        }
#pragma unroll
        for (int off = 16; off; off >>= 1) {
            contrib += __shfl_down_sync(0xffffffffu, contrib, off);
            mval    += __shfl_down_sync(0xffffffffu, mval, off);
        }
        if (lane == 0) {
            atomicAdd(&g_sum[t], contrib);
            atomicAdd(&g_cnt[t], mval);
        }
    }
}

// ---------- K5: sdf finalize ----------
__global__ void __launch_bounds__(256) k_final(float* __restrict__ out_sdf) {
    __shared__ float smr[256];
    int t = threadIdx.x;
    float cnt = g_cnt[t];
    smr[t] = cnt;
    __syncthreads();
    for (int s = 128; s > 0; s >>= 1) {
        if (t < s) smr[t] += smr[t + s];
        __syncthreads();
    }
    float mean = smr[0] * (1.0f / 256.0f);
    out_sdf[t] = g_sum[t] / cnt * mean + 1.0f;
}

// ---------- launch ----------
extern "C" void kernel_launch(void* const* d_in, const int* in_sizes, int n_in,
                              void* d_out, int out_size) {
    (void)in_sizes; (void)n_in; (void)out_size;
    const float* macro = (const float*)d_in[0];
    const float* indiv = (const float*)d_in[1];
    const unsigned char* masks = (const unsigned char*)d_in[2];
    const float* rets  = (const float*)d_in[3];
    const float* W_ih  = (const float*)d_in[4];
    const float* W_hh  = (const float*)d_in[5];
    const float* b_ih  = (const float*)d_in[6];
    const float* b_hh  = (const float*)d_in[7];
    const float* W1    = (const float*)d_in[8];
    const float* b1    = (const float*)d_in[9];
    const float* W2    = (const float*)d_in[10];
    const float* b2    = (const float*)d_in[11];
    const float* W3    = (const float*)d_in[12];
    const float* b3    = (const float*)d_in[13];

    float* out     = (float*)d_out;
    float* out_sdf = out;          // sdf [T,1]
    float* out_w   = out + T_;     // weights [1,T,N,1]

    cudaFuncSetAttribute(k_mlp, cudaFuncAttributeMaxDynamicSharedMemorySize, SMEM_MLP);

    k_prep<<<T_, G4>>>(macro, W_ih, b_ih, b_hh, masks);
    k_lstm<<<1, G4>>>(W_hh);
    k_macro1<<<T_ / 4, 256>>>(W1, b1);
    k_mlp<<<GRID_MLP, 128, SMEM_MLP>>>(indiv, masks, rets, W1, W2, b2, W3, b3, out_w);
    k_final<<<1, T_>>>(out_sdf);
}